// round 7
// baseline (speedup 1.0000x reference)
#include <cuda_runtime.h>

#define T_STEPS 2048
#define BATCH   256
#define HID     64
#define NG      256
#define NOUT    11
#define NCH     4
#define CHUNK   (T_STEPS / NCH)

typedef unsigned long long u64;

// Double-buffered inter-layer tensors (concurrent layers never alias).
__device__ float g_hbuf0[(size_t)BATCH * T_STEPS * HID];  // layer0 h
__device__ float g_hbuf1[(size_t)BATCH * T_STEPS * HID];  // layer1 h
__device__ float g_xp1[(size_t)BATCH * T_STEPS * NG];     // x-proj for layer1
__device__ float g_xp2[(size_t)BATCH * T_STEPS * NG];     // x-proj for layer2
// Chunk-carry state.
__device__ float g_cst[3][BATCH * HID];
__device__ float g_h2st[BATCH * HID];
__device__ float g_hfin[BATCH * HID];

__device__ __forceinline__ u64 pack2(float a, float b) {
    u64 r; asm("mov.b64 %0, {%1,%2};" : "=l"(r) : "f"(a), "f"(b)); return r;
}
__device__ __forceinline__ void unpack2(u64 v, float& a, float& b) {
    asm("mov.b64 {%0,%1}, %2;" : "=f"(a), "=f"(b) : "l"(v));
}
__device__ __forceinline__ void ffma2(u64& d, u64 a, u64 b) {
    asm("fma.rn.f32x2 %0, %1, %2, %0;" : "+l"(d) : "l"(a), "l"(b));
}
__device__ __forceinline__ void fadd2(u64& d, u64 a) {
    asm("add.rn.f32x2 %0, %0, %1;" : "+l"(d) : "l"(a));
}
__device__ __forceinline__ float sigf(float x) {
    return __fdividef(1.0f, 1.0f + __expf(-x));
}
__device__ __forceinline__ float tanh2(float x) { return 2.0f * sigf(2.0f * x) - 1.0f; }

__device__ __forceinline__ void gbar(int id) {
    asm volatile("bar.sync %0, 128;" :: "r"(id) : "memory");
}

// ---------------------------------------------------------------------------
// Light x-projection GEMM: 128 threads, 1 gate row/thread, ~110 regs, 32KB smem
// -> co-resident with a rec CTA on the same SM (fills rec's idle issue slots).
// CTA covers 128 m-rows x 128 gate-rows (rh half). Grid/chunk = 2048 CTAs.
// LAYER=1: g_hbuf0 -> g_xp1 ; LAYER=2: g_hbuf1 -> g_xp2.
// ---------------------------------------------------------------------------
template<int LAYER>
__global__ __launch_bounds__(128, 1)
void xproj_lite(const float* __restrict__ W_ih,
                const float* __restrict__ b_ih,
                const float* __restrict__ b_hh,
                int t0)
{
    __shared__ __align__(16) float sh[128 * HID];   // 32 KB
    const float* hsrc = (LAYER == 1) ? g_hbuf0 : g_hbuf1;
    float*       xpd  = (LAYER == 1) ? g_xp1   : g_xp2;

    const int tid = threadIdx.x;
    const int c   = blockIdx.x;
    const int bg   = c >> 3;
    const int rem  = c & 7;
    const int tile = rem >> 1;
    const int rh   = rem & 1;
    const size_t m0 = (size_t)bg * T_STEPS + t0 + tile * 128;

    {   // tile load: 2048 float4, 16/thread
        const float4* src = (const float4*)(hsrc + m0 * HID);
        float4* dst = (float4*)sh;
#pragma unroll
        for (int i = 0; i < 16; i++) dst[tid + i * 128] = src[tid + i * 128];
    }

    const int row = rh * 128 + tid;
    u64 w[32];
    {
        const float4* p = (const float4*)(W_ih + row * HID);
#pragma unroll
        for (int i = 0; i < 16; i++) {
            float4 v = p[i];
            w[2 * i] = pack2(v.x, v.y); w[2 * i + 1] = pack2(v.z, v.w);
        }
    }
    const float bias = b_ih[row] + b_hh[row];
    __syncthreads();

    float* out = xpd + m0 * NG + row;
#pragma unroll 2
    for (int m = 0; m < 128; m++) {
        const ulonglong2* hr = (const ulonglong2*)(sh + m * HID);
        u64 a0 = 0, a1 = 0;
#pragma unroll
        for (int k = 0; k < 16; k++) {
            ulonglong2 pv = hr[k];
            ffma2(a0, pv.x, w[2 * k]); ffma2(a1, pv.y, w[2 * k + 1]);
        }
        fadd2(a0, a1);
        float x, y; unpack2(a0, x, y);
        out[(size_t)m * NG] = bias + x + y;
    }
}

// ---------------------------------------------------------------------------
// Recurrent chunk kernel (R6 loop body, chunked). CTA = 2 elems, 256 thr.
// Carries (h, c) across chunks via g_hbuf*/g_cst/g_h2st.
// MODE 0: x -> g_hbuf0 ; MODE 1: g_xp1 -> g_hbuf1 ; MODE 2: g_xp2 -> g_hfin.
// ---------------------------------------------------------------------------
template<int MODE>
__global__ __launch_bounds__(256, 1)
void lstm_rec(int t0,
              const float* __restrict__ x_in,
              const float* __restrict__ W_hh,
              const float* __restrict__ W_ih,
              const float* __restrict__ b_ih,
              const float* __restrict__ b_hh)
{
    __shared__ __align__(16) float sh[2][2][HID];
    __shared__ float sx[2][2][2];

    const float* xpsrc = (MODE == 1) ? g_xp1   : g_xp2;
    float*       hout  = (MODE == 0) ? g_hbuf0 : g_hbuf1;   // MODE2: unused

    const int tid  = threadIdx.x;
    const int be   = tid >> 7;
    const int r    = tid & 127;
    const int j    = r >> 1;
    const int role = r & 1;
    const int bg   = blockIdx.x * 2 + be;
    const int bid  = be + 1;
    const int t1   = t0 + CHUNK;

    const int rowA = role ? (64 + j) : j;
    const int rowB = rowA + 128;

    u64 wA[32], wB[32];
    {
        const float4* pa = (const float4*)(W_hh + rowA * HID);
        const float4* pb = (const float4*)(W_hh + rowB * HID);
#pragma unroll
        for (int i = 0; i < 16; i++) {
            float4 va = pa[i], vb = pb[i];
            wA[2 * i] = pack2(va.x, va.y); wA[2 * i + 1] = pack2(va.z, va.w);
            wB[2 * i] = pack2(vb.x, vb.y); wB[2 * i + 1] = pack2(vb.z, vb.w);
        }
    }

    float biasA = 0.f, biasB = 0.f, wxA0 = 0.f, wxA1 = 0.f, wxB0 = 0.f, wxB1 = 0.f;
    if (MODE == 0) {
        biasA = b_ih[rowA] + b_hh[rowA];
        biasB = b_ih[rowB] + b_hh[rowB];
        wxA0 = W_ih[rowA * 2]; wxA1 = W_ih[rowA * 2 + 1];
        wxB0 = W_ih[rowB * 2]; wxB1 = W_ih[rowB * 2 + 1];
    }

    // ---- chunk-carry h init ----
    if (role) {
        float h0 = 0.f;
        if (t0 > 0) {
            if (MODE == 2) h0 = g_h2st[bg * HID + j];
            else           h0 = hout[(size_t)bg * T_STEPS * HID + (size_t)(t0 - 1) * HID + j];
        }
        sh[0][be][j] = h0;
    }

    float xn0 = 0.f, xn1 = 0.f;
    if (MODE == 0 && r == 0) {
        const float2* xq = (const float2*)(x_in + (size_t)bg * T_STEPS * 2);
        float2 x0 = xq[t0]; sx[0][be][0] = x0.x; sx[0][be][1] = x0.y;
        float2 x1 = xq[t0 + 1]; xn0 = x1.x; xn1 = x1.y;
    }

    const float* xpb = xpsrc + (size_t)bg * T_STEPS * NG;
    float xpA0 = 0.f, xpB0 = 0.f, xpA1 = 0.f, xpB1 = 0.f;
    if (MODE >= 1) {
        xpA0 = xpb[(size_t)t0 * NG + rowA];       xpB0 = xpb[(size_t)t0 * NG + rowB];
        xpA1 = xpb[(size_t)(t0 + 1) * NG + rowA]; xpB1 = xpb[(size_t)(t0 + 1) * NG + rowB];
    }

    float c = (t0 > 0) ? g_cst[MODE][bg * HID + j] : 0.f;   // used by role1 only
    float hl = 0.f;
    float* hb = hout + (size_t)bg * T_STEPS * HID + j;
    __syncthreads();

    for (int t = t0; t < t1; t++) {
        const int p = t & 1;
        const ulonglong2* hr = (const ulonglong2*)sh[p][be];
        u64 aA0 = 0, aA1 = 0, aB0 = 0, aB1 = 0;
#pragma unroll
        for (int k = 0; k < 16; k++) {
            ulonglong2 pv = hr[k];
            ffma2(aA0, pv.x, wA[2 * k]); ffma2(aA1, pv.y, wA[2 * k + 1]);
            ffma2(aB0, pv.x, wB[2 * k]); ffma2(aB1, pv.y, wB[2 * k + 1]);
        }
        float zA, zB;
        {
            float u0, u1, u2, u3;
            unpack2(aA0, u0, u1); unpack2(aA1, u2, u3); zA = (u0 + u1) + (u2 + u3);
            unpack2(aB0, u0, u1); unpack2(aB1, u2, u3); zB = (u0 + u1) + (u2 + u3);
        }
        if (MODE == 0) {
            float xv0 = sx[p][be][0], xv1 = sx[p][be][1];
            zA += biasA + wxA0 * xv0 + wxA1 * xv1;
            zB += biasB + wxB0 * xv0 + wxB1 * xv1;
        } else {
            zA += xpA0; zB += xpB0;
        }

        if (MODE >= 1) {
            xpA0 = xpA1; xpB0 = xpB1;
            int tn = (t + 2 < T_STEPS) ? (t + 2) : (T_STEPS - 1);
            xpA1 = xpb[(size_t)tn * NG + rowA];
            xpB1 = xpb[(size_t)tn * NG + rowB];
        }

        float sA    = sigf(zA);
        float other = role ? sigf(zB) : tanh2(zB);
        float send  = sA * other;
        float ar    = __shfl_xor_sync(0xffffffffu, send, 1);
        if (role) {
            c = sA * c + ar;
            float h = other * tanh2(c);
            hl = h;
            sh[p ^ 1][be][j] = h;
            if (MODE <= 1) hb[(size_t)t * HID] = h;
            if (MODE == 2 && t == T_STEPS - 1) g_hfin[bg * HID + j] = h;
        }
        if (MODE == 0 && r == 0) {
            sx[p ^ 1][be][0] = xn0; sx[p ^ 1][be][1] = xn1;
            int tn = (t + 2 < T_STEPS) ? (t + 2) : (T_STEPS - 1);
            const float2* xq = (const float2*)(x_in + (size_t)bg * T_STEPS * 2);
            float2 xv = xq[tn]; xn0 = xv.x; xn1 = xv.y;
        }
        gbar(bid);
    }

    // ---- chunk-carry state save ----
    if (role) {
        g_cst[MODE][bg * HID + j] = c;
        if (MODE == 2) g_h2st[bg * HID + j] = hl;
    }
}

__global__ void final_linear_kernel(const float* __restrict__ W_out,
                                    const float* __restrict__ b_out,
                                    float* __restrict__ out)
{
    int idx = blockIdx.x * blockDim.x + threadIdx.x;
    if (idx >= BATCH * NOUT) return;
    int b = idx / NOUT, o = idx - b * NOUT;
    float s = b_out[o];
    const float* h  = &g_hfin[b * HID];
    const float* wr = &W_out[o * HID];
#pragma unroll 16
    for (int k = 0; k < HID; k++) s += h[k] * wr[k];
    out[idx] = s;
}

// ---------------------------------------------------------------------------
// Multi-stream chunk pipeline (graph-capture fork/join via events).
// ---------------------------------------------------------------------------
extern "C" void kernel_launch(void* const* d_in, const int* in_sizes, int n_in,
                              void* d_out, int out_size)
{
    const float* x    = (const float*)d_in[0];
    const float* Wih0 = (const float*)d_in[1];
    const float* Whh0 = (const float*)d_in[2];
    const float* bih0 = (const float*)d_in[3];
    const float* bhh0 = (const float*)d_in[4];
    const float* Wih1 = (const float*)d_in[5];
    const float* Whh1 = (const float*)d_in[6];
    const float* bih1 = (const float*)d_in[7];
    const float* bhh1 = (const float*)d_in[8];
    const float* Wih2 = (const float*)d_in[9];
    const float* Whh2 = (const float*)d_in[10];
    const float* bih2 = (const float*)d_in[11];
    const float* bhh2 = (const float*)d_in[12];
    const float* Wout = (const float*)d_in[13];
    const float* bout = (const float*)d_in[14];

    // One-time stream/event creation (host objects, not device memory).
    static cudaStream_t s1, s2, s3;
    static cudaEvent_t eR0[NCH], eG1[NCH], eR1[NCH], eG2[NCH];
    static bool inited = []() {
        cudaStreamCreateWithFlags(&s1, cudaStreamNonBlocking);
        cudaStreamCreateWithFlags(&s2, cudaStreamNonBlocking);
        cudaStreamCreateWithFlags(&s3, cudaStreamNonBlocking);
        for (int k = 0; k < NCH; k++) {
            cudaEventCreateWithFlags(&eR0[k], cudaEventDisableTiming);
            cudaEventCreateWithFlags(&eG1[k], cudaEventDisableTiming);
            cudaEventCreateWithFlags(&eR1[k], cudaEventDisableTiming);
            cudaEventCreateWithFlags(&eG2[k], cudaEventDisableTiming);
        }
        return true;
    }();
    (void)inited;

    dim3 rgrid(BATCH / 2), rblock(256);
    dim3 ggrid(BATCH * 8), gblock(128);   // 2048 CTAs per chunk

    // Stage 0 (stream 0): layer-0 recurrence, chunked.
    for (int k = 0; k < NCH; k++) {
        lstm_rec<0><<<rgrid, rblock>>>(k * CHUNK, x, Whh0, Wih0, bih0, bhh0);
        cudaEventRecord(eR0[k], 0);
    }
    // Stage 1 (s1): x-projection for layer 1.
    for (int k = 0; k < NCH; k++) {
        cudaStreamWaitEvent(s1, eR0[k], 0);
        xproj_lite<1><<<ggrid, gblock, 0, s1>>>(Wih1, bih1, bhh1, k * CHUNK);
        cudaEventRecord(eG1[k], s1);
    }
    // Stage 2 (s2): layer-1 recurrence.
    for (int k = 0; k < NCH; k++) {
        cudaStreamWaitEvent(s2, eG1[k], 0);
        lstm_rec<1><<<rgrid, rblock, 0, s2>>>(k * CHUNK, nullptr, Whh1, nullptr, nullptr, nullptr);
        cudaEventRecord(eR1[k], s2);
    }
    // Stage 3 (s3): x-projection for layer 2.
    for (int k = 0; k < NCH; k++) {
        cudaStreamWaitEvent(s3, eR1[k], 0);
        xproj_lite<2><<<ggrid, gblock, 0, s3>>>(Wih2, bih2, bhh2, k * CHUNK);
        cudaEventRecord(eG2[k], s3);
    }
    // Stage 4 (stream 0): layer-2 recurrence, then head. Joins all streams.
    for (int k = 0; k < NCH; k++) {
        cudaStreamWaitEvent(0, eG2[k], 0);
        lstm_rec<2><<<rgrid, rblock>>>(k * CHUNK, nullptr, Whh2, nullptr, nullptr, nullptr);
    }
    final_linear_kernel<<<(BATCH * NOUT + 255) / 256, 256>>>(Wout, bout, (float*)d_out);
}

// round 8
// speedup vs baseline: 1.9146x; 1.9146x over previous
#include <cuda_runtime.h>

#define T_STEPS 2048
#define BATCH   256
#define HID     64
#define NG      256
#define NOUT    11

typedef unsigned long long u64;

__device__ float g_hbuf[(size_t)BATCH * T_STEPS * HID];   // 128 MB
__device__ float g_xp[(size_t)BATCH * T_STEPS * NG];      // 512 MB
__device__ float g_hfin[BATCH * HID];

__device__ __forceinline__ u64 pack2(float a, float b) {
    u64 r; asm("mov.b64 %0, {%1,%2};" : "=l"(r) : "f"(a), "f"(b)); return r;
}
__device__ __forceinline__ void unpack2(u64 v, float& a, float& b) {
    asm("mov.b64 {%0,%1}, %2;" : "=f"(a), "=f"(b) : "l"(v));
}
__device__ __forceinline__ void ffma2(u64& d, u64 a, u64 b) {
    asm("fma.rn.f32x2 %0, %1, %2, %0;" : "+l"(d) : "l"(a), "l"(b));
}
__device__ __forceinline__ void fadd2(u64& d, u64 a) {
    asm("add.rn.f32x2 %0, %0, %1;" : "+l"(d) : "l"(a));
}

// HW tanh: single MUFU.TANH, 16 cyc (vs ~50-cyc EX2/RCP chains).
__device__ __forceinline__ float tanha(float x) {
    float y; asm("tanh.approx.f32 %0, %1;" : "=f"(y) : "f"(x)); return y;
}
__device__ __forceinline__ float sigt(float x) {
    return fmaf(0.5f, tanha(0.5f * x), 0.5f);
}

__device__ __forceinline__ void gbar(int id) {
    asm volatile("bar.sync %0, 128;" :: "r"(id) : "memory");
}

// ---------------------------------------------------------------------------
// Bulk x-projection (R4 version -- measured 427us).
// ---------------------------------------------------------------------------
__global__ __launch_bounds__(256, 1)
void xproj_gemm(const float* __restrict__ W_ih,
                const float* __restrict__ b_ih,
                const float* __restrict__ b_hh)
{
    __shared__ __align__(16) float sh[256 * HID];
    const int tid = threadIdx.x;
    const size_t m0 = (size_t)blockIdx.x * 256;

    {
        const float4* src = (const float4*)(g_hbuf + m0 * HID);
        float4* dst = (float4*)sh;
#pragma unroll
        for (int i = 0; i < 16; i++) dst[tid + i * 256] = src[tid + i * 256];
    }

    const int rowA = tid & 127;
    const int rowB = rowA + 128;
    const int mlo  = (tid >> 7) * 128;

    u64 wA[32], wB[32];
    {
        const float4* pa = (const float4*)(W_ih + rowA * HID);
        const float4* pb = (const float4*)(W_ih + rowB * HID);
#pragma unroll
        for (int i = 0; i < 16; i++) {
            float4 va = pa[i], vb = pb[i];
            wA[2 * i] = pack2(va.x, va.y); wA[2 * i + 1] = pack2(va.z, va.w);
            wB[2 * i] = pack2(vb.x, vb.y); wB[2 * i + 1] = pack2(vb.z, vb.w);
        }
    }
    const float biasA = b_ih[rowA] + b_hh[rowA];
    const float biasB = b_ih[rowB] + b_hh[rowB];
    __syncthreads();

    float* out = g_xp + (m0 + mlo) * NG;
#pragma unroll 2
    for (int m = 0; m < 128; m++) {
        const ulonglong2* hr = (const ulonglong2*)(sh + (mlo + m) * HID);
        u64 aA0 = 0, aA1 = 0, aB0 = 0, aB1 = 0;
#pragma unroll
        for (int k = 0; k < 16; k++) {
            ulonglong2 pv = hr[k];
            ffma2(aA0, pv.x, wA[2 * k]); ffma2(aA1, pv.y, wA[2 * k + 1]);
            ffma2(aB0, pv.x, wB[2 * k]); ffma2(aB1, pv.y, wB[2 * k + 1]);
        }
        fadd2(aA0, aA1); fadd2(aB0, aB1);
        float x, y;
        unpack2(aA0, x, y); out[(size_t)m * NG + rowA] = biasA + x + y;
        unpack2(aB0, x, y); out[(size_t)m * NG + rowB] = biasB + x + y;
    }
}

// ---------------------------------------------------------------------------
// Recurrent kernel: R6 structure (best measured), activations -> MUFU.TANH.
// ---------------------------------------------------------------------------
template<int MODE>
__global__ __launch_bounds__(256, 1)
void lstm_rec(const float* __restrict__ x_in,
              const float* __restrict__ W_hh,
              const float* __restrict__ W_ih,
              const float* __restrict__ b_ih,
              const float* __restrict__ b_hh)
{
    __shared__ __align__(16) float sh[2][2][HID];
    __shared__ float sx[2][2][2];

    const int tid  = threadIdx.x;
    const int be   = tid >> 7;
    const int r    = tid & 127;
    const int j    = r >> 1;
    const int role = r & 1;
    const int bg   = blockIdx.x * 2 + be;
    const int bid  = be + 1;

    const int rowA = role ? (64 + j) : j;         // (i|f)
    const int rowB = rowA + 128;                  // (g|o)

    u64 wA[32], wB[32];
    {
        const float4* pa = (const float4*)(W_hh + rowA * HID);
        const float4* pb = (const float4*)(W_hh + rowB * HID);
#pragma unroll
        for (int i = 0; i < 16; i++) {
            float4 va = pa[i], vb = pb[i];
            wA[2 * i] = pack2(va.x, va.y); wA[2 * i + 1] = pack2(va.z, va.w);
            wB[2 * i] = pack2(vb.x, vb.y); wB[2 * i + 1] = pack2(vb.z, vb.w);
        }
    }

    float biasA = 0.f, biasB = 0.f, wxA0 = 0.f, wxA1 = 0.f, wxB0 = 0.f, wxB1 = 0.f;
    if (MODE == 0) {
        biasA = b_ih[rowA] + b_hh[rowA];
        biasB = b_ih[rowB] + b_hh[rowB];
        wxA0 = W_ih[rowA * 2]; wxA1 = W_ih[rowA * 2 + 1];
        wxB0 = W_ih[rowB * 2]; wxB1 = W_ih[rowB * 2 + 1];
    }

    if (role) sh[0][be][j] = 0.f;

    float xn0 = 0.f, xn1 = 0.f;
    if (MODE == 0 && r == 0) {
        const float2* xq = (const float2*)(x_in + (size_t)bg * T_STEPS * 2);
        float2 x0 = xq[0]; sx[0][be][0] = x0.x; sx[0][be][1] = x0.y;
        float2 x1 = xq[1]; xn0 = x1.x; xn1 = x1.y;
    }

    const float* xpb = g_xp + (size_t)bg * T_STEPS * NG;
    float xpA0 = 0.f, xpB0 = 0.f, xpA1 = 0.f, xpB1 = 0.f;
    if (MODE >= 1) {
        xpA0 = xpb[rowA];      xpB0 = xpb[rowB];
        xpA1 = xpb[NG + rowA]; xpB1 = xpb[NG + rowB];
    }

    float c = 0.f;
    float* hb = g_hbuf + (size_t)bg * T_STEPS * HID + j;
    __syncthreads();

    for (int t = 0; t < T_STEPS; t++) {
        const int p = t & 1;
        const ulonglong2* hr = (const ulonglong2*)sh[p][be];
        u64 aA0 = 0, aA1 = 0, aB0 = 0, aB1 = 0;
#pragma unroll
        for (int k = 0; k < 16; k++) {
            ulonglong2 pv = hr[k];                 // broadcast LDS.128
            ffma2(aA0, pv.x, wA[2 * k]); ffma2(aA1, pv.y, wA[2 * k + 1]);
            ffma2(aB0, pv.x, wB[2 * k]); ffma2(aB1, pv.y, wB[2 * k + 1]);
        }
        float zA, zB;
        {
            float u0, u1, u2, u3;
            unpack2(aA0, u0, u1); unpack2(aA1, u2, u3); zA = (u0 + u1) + (u2 + u3);
            unpack2(aB0, u0, u1); unpack2(aB1, u2, u3); zB = (u0 + u1) + (u2 + u3);
        }
        if (MODE == 0) {
            float xv0 = sx[p][be][0], xv1 = sx[p][be][1];
            zA += biasA + wxA0 * xv0 + wxA1 * xv1;
            zB += biasB + wxB0 * xv0 + wxB1 * xv1;
        } else {
            zA += xpA0; zB += xpB0;
        }

        if (MODE >= 1) {
            xpA0 = xpA1; xpB0 = xpB1;
            int tn = (t + 2 < T_STEPS) ? (t + 2) : (T_STEPS - 1);
            xpA1 = xpb[(size_t)tn * NG + rowA];
            xpB1 = xpb[(size_t)tn * NG + rowB];
        }

        // activations on HW MUFU.TANH
        float sA    = sigt(zA);                        // sig(i) | sig(f)
        float other = role ? sigt(zB) : tanha(zB);     // sig(o) | tanh(g)
        float send  = sA * other;                      // i*tanh(g) | --
        float ar    = __shfl_xor_sync(0xffffffffu, send, 1);
        if (role) {
            c = sA * c + ar;
            float h = other * tanha(c);
            sh[p ^ 1][be][j] = h;
            if (MODE <= 1) hb[(size_t)t * HID] = h;
            if (MODE == 2 && t == T_STEPS - 1) g_hfin[bg * HID + j] = h;
        }
        if (MODE == 0 && r == 0) {
            sx[p ^ 1][be][0] = xn0; sx[p ^ 1][be][1] = xn1;
            int tn = (t + 2 < T_STEPS) ? (t + 2) : (T_STEPS - 1);
            const float2* xq = (const float2*)(x_in + (size_t)bg * T_STEPS * 2);
            float2 xv = xq[tn]; xn0 = xv.x; xn1 = xv.y;
        }
        gbar(bid);
    }
}

__global__ void final_linear_kernel(const float* __restrict__ W_out,
                                    const float* __restrict__ b_out,
                                    float* __restrict__ out)
{
    int idx = blockIdx.x * blockDim.x + threadIdx.x;
    if (idx >= BATCH * NOUT) return;
    int b = idx / NOUT, o = idx - b * NOUT;
    float s = b_out[o];
    const float* h  = &g_hfin[b * HID];
    const float* wr = &W_out[o * HID];
#pragma unroll 16
    for (int k = 0; k < HID; k++) s += h[k] * wr[k];
    out[idx] = s;
}

extern "C" void kernel_launch(void* const* d_in, const int* in_sizes, int n_in,
                              void* d_out, int out_size)
{
    const float* x    = (const float*)d_in[0];
    const float* Wih0 = (const float*)d_in[1];
    const float* Whh0 = (const float*)d_in[2];
    const float* bih0 = (const float*)d_in[3];
    const float* bhh0 = (const float*)d_in[4];
    const float* Wih1 = (const float*)d_in[5];
    const float* Whh1 = (const float*)d_in[6];
    const float* bih1 = (const float*)d_in[7];
    const float* bhh1 = (const float*)d_in[8];
    const float* Wih2 = (const float*)d_in[9];
    const float* Whh2 = (const float*)d_in[10];
    const float* bih2 = (const float*)d_in[11];
    const float* bhh2 = (const float*)d_in[12];
    const float* Wout = (const float*)d_in[13];
    const float* bout = (const float*)d_in[14];

    dim3 rgrid(BATCH / 2), rblock(256);
    dim3 ggrid(BATCH * T_STEPS / 256), gblock(256);

    lstm_rec<0><<<rgrid, rblock>>>(x, Whh0, Wih0, bih0, bhh0);
    xproj_gemm<<<ggrid, gblock>>>(Wih1, bih1, bhh1);
    lstm_rec<1><<<rgrid, rblock>>>(nullptr, Whh1, nullptr, nullptr, nullptr);
    xproj_gemm<<<ggrid, gblock>>>(Wih2, bih2, bhh2);
    lstm_rec<2><<<rgrid, rblock>>>(nullptr, Whh2, nullptr, nullptr, nullptr);
    final_linear_kernel<<<(BATCH * NOUT + 255) / 256, 256>>>(Wout, bout, (float*)d_out);
}

// round 9
// speedup vs baseline: 1.9161x; 1.0008x over previous
#include <cuda_runtime.h>

#define T_STEPS 2048
#define BATCH   256
#define HID     64
#define NG      256
#define NOUT    11

typedef unsigned long long u64;

__device__ float g_hbuf[(size_t)BATCH * T_STEPS * HID];   // 128 MB
__device__ float g_xp[(size_t)BATCH * T_STEPS * NG];      // 512 MB
__device__ float g_hfin[BATCH * HID];

__device__ __forceinline__ u64 pack2(float a, float b) {
    u64 r; asm("mov.b64 %0, {%1,%2};" : "=l"(r) : "f"(a), "f"(b)); return r;
}
__device__ __forceinline__ void unpack2(u64 v, float& a, float& b) {
    asm("mov.b64 {%0,%1}, %2;" : "=f"(a), "=f"(b) : "l"(v));
}
__device__ __forceinline__ void ffma2(u64& d, u64 a, u64 b) {
    asm("fma.rn.f32x2 %0, %1, %2, %0;" : "+l"(d) : "l"(a), "l"(b));
}
__device__ __forceinline__ void fadd2(u64& d, u64 a) {
    asm("add.rn.f32x2 %0, %0, %1;" : "+l"(d) : "l"(a));
}

// HW tanh: single MUFU.TANH (committed R8 win).
__device__ __forceinline__ float tanha(float x) {
    float y; asm("tanh.approx.f32 %0, %1;" : "=f"(y) : "f"(x)); return y;
}
__device__ __forceinline__ float sigt(float x) {
    return fmaf(0.5f, tanha(0.5f * x), 0.5f);
}

__device__ __forceinline__ void gbar(int id) {
    asm volatile("bar.sync %0, 128;" :: "r"(id) : "memory");
}

// ---------------------------------------------------------------------------
// Bulk x-projection, v9: 2 m-rows per inner iteration (8 accumulators)
// to double ILP per dependency chain (R8 issue=38.6% -> chain-starved).
// ---------------------------------------------------------------------------
__global__ __launch_bounds__(256, 1)
void xproj_gemm(const float* __restrict__ W_ih,
                const float* __restrict__ b_ih,
                const float* __restrict__ b_hh)
{
    __shared__ __align__(16) float sh[256 * HID];
    const int tid = threadIdx.x;
    const size_t m0 = (size_t)blockIdx.x * 256;

    {
        const float4* src = (const float4*)(g_hbuf + m0 * HID);
        float4* dst = (float4*)sh;
#pragma unroll
        for (int i = 0; i < 16; i++) dst[tid + i * 256] = src[tid + i * 256];
    }

    const int rowA = tid & 127;
    const int rowB = rowA + 128;
    const int mlo  = (tid >> 7) * 128;

    u64 wA[32], wB[32];
    {
        const float4* pa = (const float4*)(W_ih + rowA * HID);
        const float4* pb = (const float4*)(W_ih + rowB * HID);
#pragma unroll
        for (int i = 0; i < 16; i++) {
            float4 va = pa[i], vb = pb[i];
            wA[2 * i] = pack2(va.x, va.y); wA[2 * i + 1] = pack2(va.z, va.w);
            wB[2 * i] = pack2(vb.x, vb.y); wB[2 * i + 1] = pack2(vb.z, vb.w);
        }
    }
    const float biasA = b_ih[rowA] + b_hh[rowA];
    const float biasB = b_ih[rowB] + b_hh[rowB];
    __syncthreads();

    float* out = g_xp + (m0 + mlo) * NG;
    for (int m = 0; m < 128; m += 2) {
        const ulonglong2* h0 = (const ulonglong2*)(sh + (mlo + m) * HID);
        const ulonglong2* h1 = (const ulonglong2*)(sh + (mlo + m + 1) * HID);
        u64 aA0 = 0, aA1 = 0, aB0 = 0, aB1 = 0;   // m-row 0
        u64 cA0 = 0, cA1 = 0, cB0 = 0, cB1 = 0;   // m-row 1
#pragma unroll
        for (int k = 0; k < 16; k++) {
            ulonglong2 p = h0[k], q = h1[k];
            ffma2(aA0, p.x, wA[2 * k]); ffma2(aA1, p.y, wA[2 * k + 1]);
            ffma2(aB0, p.x, wB[2 * k]); ffma2(aB1, p.y, wB[2 * k + 1]);
            ffma2(cA0, q.x, wA[2 * k]); ffma2(cA1, q.y, wA[2 * k + 1]);
            ffma2(cB0, q.x, wB[2 * k]); ffma2(cB1, q.y, wB[2 * k + 1]);
        }
        fadd2(aA0, aA1); fadd2(aB0, aB1); fadd2(cA0, cA1); fadd2(cB0, cB1);
        float x, y;
        unpack2(aA0, x, y); out[(size_t)m * NG + rowA]       = biasA + x + y;
        unpack2(aB0, x, y); out[(size_t)m * NG + rowB]       = biasB + x + y;
        unpack2(cA0, x, y); out[(size_t)(m + 1) * NG + rowA] = biasA + x + y;
        unpack2(cB0, x, y); out[(size_t)(m + 1) * NG + rowB] = biasB + x + y;
    }
}

// ---------------------------------------------------------------------------
// Recurrent kernel: R8 structure + forced phase stagger between the two
// batch-element groups (be=1 delays ~360 cyc once; offset self-sustains
// since both groups have identical per-step periods). Group 0's serial
// tail then overlaps group 1's matmul issue, and vice versa.
// ---------------------------------------------------------------------------
template<int MODE>
__global__ __launch_bounds__(256, 1)
void lstm_rec(const float* __restrict__ x_in,
              const float* __restrict__ W_hh,
              const float* __restrict__ W_ih,
              const float* __restrict__ b_ih,
              const float* __restrict__ b_hh)
{
    __shared__ __align__(16) float sh[2][2][HID];
    __shared__ float sx[2][2][2];
    __shared__ float sdump;                       // stagger sink (never read)

    const int tid  = threadIdx.x;
    const int be   = tid >> 7;
    const int r    = tid & 127;
    const int j    = r >> 1;
    const int role = r & 1;
    const int bg   = blockIdx.x * 2 + be;
    const int bid  = be + 1;

    const int rowA = role ? (64 + j) : j;         // (i|f)
    const int rowB = rowA + 128;                  // (g|o)

    u64 wA[32], wB[32];
    {
        const float4* pa = (const float4*)(W_hh + rowA * HID);
        const float4* pb = (const float4*)(W_hh + rowB * HID);
#pragma unroll
        for (int i = 0; i < 16; i++) {
            float4 va = pa[i], vb = pb[i];
            wA[2 * i] = pack2(va.x, va.y); wA[2 * i + 1] = pack2(va.z, va.w);
            wB[2 * i] = pack2(vb.x, vb.y); wB[2 * i + 1] = pack2(vb.z, vb.w);
        }
    }

    float biasA = 0.f, biasB = 0.f, wxA0 = 0.f, wxA1 = 0.f, wxB0 = 0.f, wxB1 = 0.f;
    if (MODE == 0) {
        biasA = b_ih[rowA] + b_hh[rowA];
        biasB = b_ih[rowB] + b_hh[rowB];
        wxA0 = W_ih[rowA * 2]; wxA1 = W_ih[rowA * 2 + 1];
        wxB0 = W_ih[rowB * 2]; wxB1 = W_ih[rowB * 2 + 1];
    }

    if (role) sh[0][be][j] = 0.f;

    float xn0 = 0.f, xn1 = 0.f;
    if (MODE == 0 && r == 0) {
        const float2* xq = (const float2*)(x_in + (size_t)bg * T_STEPS * 2);
        float2 x0 = xq[0]; sx[0][be][0] = x0.x; sx[0][be][1] = x0.y;
        float2 x1 = xq[1]; xn0 = x1.x; xn1 = x1.y;
    }

    const float* xpb = g_xp + (size_t)bg * T_STEPS * NG;
    float xpA0 = 0.f, xpB0 = 0.f, xpA1 = 0.f, xpB1 = 0.f;
    if (MODE >= 1) {
        xpA0 = xpb[rowA];      xpB0 = xpb[rowB];
        xpA1 = xpb[NG + rowA]; xpB1 = xpb[NG + rowB];
    }

    float c = 0.f;
    float* hb = g_hbuf + (size_t)bg * T_STEPS * HID + j;
    __syncthreads();

    // ---- phase stagger: group 1 burns ~360 cyc (90 dependent FMAs) ----
    if (be == 1) {
        float d = (float)tid * 1e-7f + 0.3f;
#pragma unroll
        for (int i = 0; i < 90; i++) d = fmaf(d, 0.99993f, 1e-6f);
        if (d > 1e30f) sdump = d;     // never true; compiler can't prove it
    }

    for (int t = 0; t < T_STEPS; t++) {
        const int p = t & 1;
        const ulonglong2* hr = (const ulonglong2*)sh[p][be];
        u64 aA0 = 0, aA1 = 0, aB0 = 0, aB1 = 0;
#pragma unroll
        for (int k = 0; k < 16; k++) {
            ulonglong2 pv = hr[k];                 // broadcast LDS.128
            ffma2(aA0, pv.x, wA[2 * k]); ffma2(aA1, pv.y, wA[2 * k + 1]);
            ffma2(aB0, pv.x, wB[2 * k]); ffma2(aB1, pv.y, wB[2 * k + 1]);
        }
        float zA, zB;
        {
            float u0, u1, u2, u3;
            unpack2(aA0, u0, u1); unpack2(aA1, u2, u3); zA = (u0 + u1) + (u2 + u3);
            unpack2(aB0, u0, u1); unpack2(aB1, u2, u3); zB = (u0 + u1) + (u2 + u3);
        }
        if (MODE == 0) {
            float xv0 = sx[p][be][0], xv1 = sx[p][be][1];
            zA += biasA + wxA0 * xv0 + wxA1 * xv1;
            zB += biasB + wxB0 * xv0 + wxB1 * xv1;
        } else {
            zA += xpA0; zB += xpB0;
        }

        if (MODE >= 1) {
            xpA0 = xpA1; xpB0 = xpB1;
            int tn = (t + 2 < T_STEPS) ? (t + 2) : (T_STEPS - 1);
            xpA1 = xpb[(size_t)tn * NG + rowA];
            xpB1 = xpb[(size_t)tn * NG + rowB];
        }

        float sA    = sigt(zA);                        // sig(i) | sig(f)
        float other = role ? sigt(zB) : tanha(zB);     // sig(o) | tanh(g)
        float send  = sA * other;                      // i*tanh(g) | --
        float ar    = __shfl_xor_sync(0xffffffffu, send, 1);
        if (role) {
            c = sA * c + ar;
            float h = other * tanha(c);
            sh[p ^ 1][be][j] = h;
            if (MODE <= 1) hb[(size_t)t * HID] = h;
            if (MODE == 2 && t == T_STEPS - 1) g_hfin[bg * HID + j] = h;
        }
        if (MODE == 0 && r == 0) {
            sx[p ^ 1][be][0] = xn0; sx[p ^ 1][be][1] = xn1;
            int tn = (t + 2 < T_STEPS) ? (t + 2) : (T_STEPS - 1);
            const float2* xq = (const float2*)(x_in + (size_t)bg * T_STEPS * 2);
            float2 xv = xq[tn]; xn0 = xv.x; xn1 = xv.y;
        }
        gbar(bid);
    }
}

__global__ void final_linear_kernel(const float* __restrict__ W_out,
                                    const float* __restrict__ b_out,
                                    float* __restrict__ out)
{
    int idx = blockIdx.x * blockDim.x + threadIdx.x;
    if (idx >= BATCH * NOUT) return;
    int b = idx / NOUT, o = idx - b * NOUT;
    float s = b_out[o];
    const float* h  = &g_hfin[b * HID];
    const float* wr = &W_out[o * HID];
#pragma unroll 16
    for (int k = 0; k < HID; k++) s += h[k] * wr[k];
    out[idx] = s;
}

extern "C" void kernel_launch(void* const* d_in, const int* in_sizes, int n_in,
                              void* d_out, int out_size)
{
    const float* x    = (const float*)d_in[0];
    const float* Wih0 = (const float*)d_in[1];
    const float* Whh0 = (const float*)d_in[2];
    const float* bih0 = (const float*)d_in[3];
    const float* bhh0 = (const float*)d_in[4];
    const float* Wih1 = (const float*)d_in[5];
    const float* Whh1 = (const float*)d_in[6];
    const float* bih1 = (const float*)d_in[7];
    const float* bhh1 = (const float*)d_in[8];
    const float* Wih2 = (const float*)d_in[9];
    const float* Whh2 = (const float*)d_in[10];
    const float* bih2 = (const float*)d_in[11];
    const float* bhh2 = (const float*)d_in[12];
    const float* Wout = (const float*)d_in[13];
    const float* bout = (const float*)d_in[14];

    dim3 rgrid(BATCH / 2), rblock(256);
    dim3 ggrid(BATCH * T_STEPS / 256), gblock(256);

    lstm_rec<0><<<rgrid, rblock>>>(x, Whh0, Wih0, bih0, bhh0);
    xproj_gemm<<<ggrid, gblock>>>(Wih1, bih1, bhh1);
    lstm_rec<1><<<rgrid, rblock>>>(nullptr, Whh1, nullptr, nullptr, nullptr);
    xproj_gemm<<<ggrid, gblock>>>(Wih2, bih2, bhh2);
    lstm_rec<2><<<rgrid, rblock>>>(nullptr, Whh2, nullptr, nullptr, nullptr);
    final_linear_kernel<<<(BATCH * NOUT + 255) / 256, 256>>>(Wout, bout, (float*)d_out);
}

// round 11
// speedup vs baseline: 2.0341x; 1.0616x over previous
#include <cuda_runtime.h>
#include <cuda_bf16.h>
#include <mma.h>
#include <cstdint>

using namespace nvcuda;

#define T_STEPS 2048
#define BATCH   256
#define HID     64
#define NG      256
#define NOUT    11
#define LDK     200     // padded K stride (elems); 400B, mult of 16B
#define XK      192     // 3 * HID bf16-split K

typedef unsigned long long u64;

__device__ float g_hbuf[(size_t)BATCH * T_STEPS * HID];   // 128 MB
__device__ float g_xp[(size_t)BATCH * T_STEPS * NG];      // 512 MB
__device__ float g_hfin[BATCH * HID];

// ---------------- scalar helpers (rec path, committed R8 form) -------------
__device__ __forceinline__ u64 pack2(float a, float b) {
    u64 r; asm("mov.b64 %0, {%1,%2};" : "=l"(r) : "f"(a), "f"(b)); return r;
}
__device__ __forceinline__ void unpack2(u64 v, float& a, float& b) {
    asm("mov.b64 {%0,%1}, %2;" : "=f"(a), "=f"(b) : "l"(v));
}
__device__ __forceinline__ void ffma2(u64& d, u64 a, u64 b) {
    asm("fma.rn.f32x2 %0, %1, %2, %0;" : "+l"(d) : "l"(a), "l"(b));
}
__device__ __forceinline__ float tanha(float x) {
    float y; asm("tanh.approx.f32 %0, %1;" : "=f"(y) : "f"(x)); return y;
}
__device__ __forceinline__ float sigt(float x) {
    return fmaf(0.5f, tanha(0.5f * x), 0.5f);
}
__device__ __forceinline__ void gbar(int id) {
    asm volatile("bar.sync %0, 128;" :: "r"(id) : "memory");
}

// Exact truncation split: hi = top-16-bit bf16 part (exact), lo = residual.
__device__ __forceinline__ void bsplit(float x, uint32_t& hibits, float& lo) {
    uint32_t u = __float_as_uint(x) & 0xFFFF0000u;
    hibits = u;
    lo = x - __uint_as_float(u);
}
__device__ __forceinline__ uint32_t bfpack_rn(float x0, float x1) {
    __nv_bfloat162 h = __floats2bfloat162_rn(x0, x1);
    return *(uint32_t*)&h;
}

// ---------------------------------------------------------------------------
// WMMA bf16 x-projection: g_xp[m, 0:256] = g_hbuf[m, 0:64] @ W_ih^T (no bias).
// 3-term split rows: A = [Ah | Al | Ah], B = [Wh | Wh | Wl], K = 192.
// CTA: 128 m-rows x 256 n-cols, 8 warps (4 m-blocks x 2 n-halves).
// ---------------------------------------------------------------------------
__global__ __launch_bounds__(256, 1)
void xproj_wmma(const float* __restrict__ W_ih)
{
    extern __shared__ __nv_bfloat16 xsm[];
    __nv_bfloat16* As = xsm;                 // [128][LDK]
    __nv_bfloat16* Bs = xsm + 128 * LDK;     // [256][LDK]

    const int tid = threadIdx.x;
    const int wid = tid >> 5;
    const size_t m0 = (size_t)blockIdx.x * 128;

    // ---- A fill: 2 threads per m-row, 32 floats each ----
    {
        const int row  = tid >> 1;
        const int half = (tid & 1) * 32;
        const float4* src = (const float4*)(g_hbuf + (m0 + row) * HID + half);
        __nv_bfloat16* ar = As + row * LDK + half;
#pragma unroll
        for (int i = 0; i < 8; i++) {
            float4 v = src[i];
            uint32_t h0, h1, h2, h3; float l0, l1, l2, l3;
            bsplit(v.x, h0, l0); bsplit(v.y, h1, l1);
            bsplit(v.z, h2, l2); bsplit(v.w, h3, l3);
            uint32_t hp0 = (h0 >> 16) | (h1 & 0xFFFF0000u);
            uint32_t hp1 = (h2 >> 16) | (h3 & 0xFFFF0000u);
            uint32_t lp0 = bfpack_rn(l0, l1);
            uint32_t lp1 = bfpack_rn(l2, l3);
            *(uint32_t*)(ar + 4 * i)            = hp0;
            *(uint32_t*)(ar + 4 * i + 2)        = hp1;
            *(uint32_t*)(ar + 64 + 4 * i)       = lp0;
            *(uint32_t*)(ar + 64 + 4 * i + 2)   = lp1;
            *(uint32_t*)(ar + 128 + 4 * i)      = hp0;
            *(uint32_t*)(ar + 128 + 4 * i + 2)  = hp1;
        }
    }
    // ---- B fill: 1 thread per gate-row (256) ----
    {
        const int n = tid;
        const float4* src = (const float4*)(W_ih + n * HID);
        __nv_bfloat16* br = Bs + n * LDK;
#pragma unroll
        for (int i = 0; i < 8; i++) {
            float4 v = src[i * 2];
            float4 w = src[i * 2 + 1];
            uint32_t h0, h1, h2, h3, h4, h5, h6, h7;
            float l0, l1, l2, l3, l4, l5, l6, l7;
            bsplit(v.x, h0, l0); bsplit(v.y, h1, l1);
            bsplit(v.z, h2, l2); bsplit(v.w, h3, l3);
            bsplit(w.x, h4, l4); bsplit(w.y, h5, l5);
            bsplit(w.z, h6, l6); bsplit(w.w, h7, l7);
            uint32_t hp0 = (h0 >> 16) | (h1 & 0xFFFF0000u);
            uint32_t hp1 = (h2 >> 16) | (h3 & 0xFFFF0000u);
            uint32_t hp2 = (h4 >> 16) | (h5 & 0xFFFF0000u);
            uint32_t hp3 = (h6 >> 16) | (h7 & 0xFFFF0000u);
            *(uint32_t*)(br + 8 * i)           = hp0;
            *(uint32_t*)(br + 8 * i + 2)       = hp1;
            *(uint32_t*)(br + 8 * i + 4)       = hp2;
            *(uint32_t*)(br + 8 * i + 6)       = hp3;
            *(uint32_t*)(br + 64 + 8 * i)      = hp0;
            *(uint32_t*)(br + 64 + 8 * i + 2)  = hp1;
            *(uint32_t*)(br + 64 + 8 * i + 4)  = hp2;
            *(uint32_t*)(br + 64 + 8 * i + 6)  = hp3;
            *(uint32_t*)(br + 128 + 8 * i)     = bfpack_rn(l0, l1);
            *(uint32_t*)(br + 128 + 8 * i + 2) = bfpack_rn(l2, l3);
            *(uint32_t*)(br + 128 + 8 * i + 4) = bfpack_rn(l4, l5);
            *(uint32_t*)(br + 128 + 8 * i + 6) = bfpack_rn(l6, l7);
        }
    }
    __syncthreads();

    // ---- compute: warp (mw, nw) -> rows [mw*32, +32), cols [nw*128, +128) ----
    const int mw = wid & 3;
    const int nw = wid >> 2;
    const __nv_bfloat16* a0p = As + (mw * 32) * LDK;
    const __nv_bfloat16* a1p = As + (mw * 32 + 16) * LDK;

#pragma unroll
    for (int nt = 0; nt < 8; nt++) {
        const int n0 = nw * 128 + nt * 16;
        wmma::fragment<wmma::accumulator, 16, 16, 16, float> c0, c1;
        wmma::fill_fragment(c0, 0.0f);
        wmma::fill_fragment(c1, 0.0f);
#pragma unroll
        for (int k = 0; k < 12; k++) {
            wmma::fragment<wmma::matrix_a, 16, 16, 16, __nv_bfloat16, wmma::row_major> a0, a1;
            wmma::fragment<wmma::matrix_b, 16, 16, 16, __nv_bfloat16, wmma::col_major> b;
            wmma::load_matrix_sync(a0, a0p + k * 16, LDK);
            wmma::load_matrix_sync(a1, a1p + k * 16, LDK);
            wmma::load_matrix_sync(b, Bs + n0 * LDK + k * 16, LDK);
            wmma::mma_sync(c0, a0, b, c0);
            wmma::mma_sync(c1, a1, b, c1);
        }
        float* o = g_xp + (m0 + (size_t)(mw * 32)) * NG + n0;
        wmma::store_matrix_sync(o, c0, NG, wmma::mem_row_major);
        wmma::store_matrix_sync(o + (size_t)16 * NG, c1, NG, wmma::mem_row_major);
    }
}

// ---------------------------------------------------------------------------
// Recurrent kernel (committed R8 form; bias added in rec for all modes).
// ---------------------------------------------------------------------------
template<int MODE>
__global__ __launch_bounds__(256, 1)
void lstm_rec(const float* __restrict__ x_in,
              const float* __restrict__ W_hh,
              const float* __restrict__ W_ih,
              const float* __restrict__ b_ih,
              const float* __restrict__ b_hh)
{
    __shared__ __align__(16) float sh[2][2][HID];
    __shared__ float sx[2][2][2];

    const int tid  = threadIdx.x;
    const int be   = tid >> 7;
    const int r    = tid & 127;
    const int j    = r >> 1;
    const int role = r & 1;
    const int bg   = blockIdx.x * 2 + be;
    const int bid  = be + 1;

    const int rowA = role ? (64 + j) : j;         // (i|f)
    const int rowB = rowA + 128;                  // (g|o)

    u64 wA[32], wB[32];
    {
        const float4* pa = (const float4*)(W_hh + rowA * HID);
        const float4* pb = (const float4*)(W_hh + rowB * HID);
#pragma unroll
        for (int i = 0; i < 16; i++) {
            float4 va = pa[i], vb = pb[i];
            wA[2 * i] = pack2(va.x, va.y); wA[2 * i + 1] = pack2(va.z, va.w);
            wB[2 * i] = pack2(vb.x, vb.y); wB[2 * i + 1] = pack2(vb.z, vb.w);
        }
    }

    const float biasA = b_ih[rowA] + b_hh[rowA];
    const float biasB = b_ih[rowB] + b_hh[rowB];
    float wxA0 = 0.f, wxA1 = 0.f, wxB0 = 0.f, wxB1 = 0.f;
    if (MODE == 0) {
        wxA0 = W_ih[rowA * 2]; wxA1 = W_ih[rowA * 2 + 1];
        wxB0 = W_ih[rowB * 2]; wxB1 = W_ih[rowB * 2 + 1];
    }

    if (role) sh[0][be][j] = 0.f;

    float xn0 = 0.f, xn1 = 0.f;
    if (MODE == 0 && r == 0) {
        const float2* xq = (const float2*)(x_in + (size_t)bg * T_STEPS * 2);
        float2 x0 = xq[0]; sx[0][be][0] = x0.x; sx[0][be][1] = x0.y;
        float2 x1 = xq[1]; xn0 = x1.x; xn1 = x1.y;
    }

    const float* xpb = g_xp + (size_t)bg * T_STEPS * NG;
    float xpA0 = 0.f, xpB0 = 0.f, xpA1 = 0.f, xpB1 = 0.f;
    if (MODE >= 1) {
        xpA0 = xpb[rowA];      xpB0 = xpb[rowB];
        xpA1 = xpb[NG + rowA]; xpB1 = xpb[NG + rowB];
    }

    float c = 0.f;
    float* hb = g_hbuf + (size_t)bg * T_STEPS * HID + j;
    __syncthreads();

    for (int t = 0; t < T_STEPS; t++) {
        const int p = t & 1;
        const ulonglong2* hr = (const ulonglong2*)sh[p][be];
        u64 aA0 = 0, aA1 = 0, aB0 = 0, aB1 = 0;
#pragma unroll
        for (int k = 0; k < 16; k++) {
            ulonglong2 pv = hr[k];                 // broadcast LDS.128
            ffma2(aA0, pv.x, wA[2 * k]); ffma2(aA1, pv.y, wA[2 * k + 1]);
            ffma2(aB0, pv.x, wB[2 * k]); ffma2(aB1, pv.y, wB[2 * k + 1]);
        }
        float zA, zB;
        {
            float u0, u1, u2, u3;
            unpack2(aA0, u0, u1); unpack2(aA1, u2, u3); zA = (u0 + u1) + (u2 + u3);
            unpack2(aB0, u0, u1); unpack2(aB1, u2, u3); zB = (u0 + u1) + (u2 + u3);
        }
        if (MODE == 0) {
            float xv0 = sx[p][be][0], xv1 = sx[p][be][1];
            zA += biasA + wxA0 * xv0 + wxA1 * xv1;
            zB += biasB + wxB0 * xv0 + wxB1 * xv1;
        } else {
            zA += xpA0 + biasA; zB += xpB0 + biasB;
        }

        if (MODE >= 1) {
            xpA0 = xpA1; xpB0 = xpB1;
            int tn = (t + 2 < T_STEPS) ? (t + 2) : (T_STEPS - 1);
            xpA1 = xpb[(size_t)tn * NG + rowA];
            xpB1 = xpb[(size_t)tn * NG + rowB];
        }

        float sA    = sigt(zA);                        // sig(i) | sig(f)
        float other = role ? sigt(zB) : tanha(zB);     // sig(o) | tanh(g)
        float send  = sA * other;                      // i*tanh(g) | --
        float ar    = __shfl_xor_sync(0xffffffffu, send, 1);
        if (role) {
            c = sA * c + ar;
            float h = other * tanha(c);
            sh[p ^ 1][be][j] = h;
            if (MODE <= 1) hb[(size_t)t * HID] = h;
            if (MODE == 2 && t == T_STEPS - 1) g_hfin[bg * HID + j] = h;
        }
        if (MODE == 0 && r == 0) {
            sx[p ^ 1][be][0] = xn0; sx[p ^ 1][be][1] = xn1;
            int tn = (t + 2 < T_STEPS) ? (t + 2) : (T_STEPS - 1);
            const float2* xq = (const float2*)(x_in + (size_t)bg * T_STEPS * 2);
            float2 xv = xq[tn]; xn0 = xv.x; xn1 = xv.y;
        }
        gbar(bid);
    }
}

__global__ void final_linear_kernel(const float* __restrict__ W_out,
                                    const float* __restrict__ b_out,
                                    float* __restrict__ out)
{
    int idx = blockIdx.x * blockDim.x + threadIdx.x;
    if (idx >= BATCH * NOUT) return;
    int b = idx / NOUT, o = idx - b * NOUT;
    float s = b_out[o];
    const float* h  = &g_hfin[b * HID];
    const float* wr = &W_out[o * HID];
#pragma unroll 16
    for (int k = 0; k < HID; k++) s += h[k] * wr[k];
    out[idx] = s;
}

extern "C" void kernel_launch(void* const* d_in, const int* in_sizes, int n_in,
                              void* d_out, int out_size)
{
    const float* x    = (const float*)d_in[0];
    const float* Wih0 = (const float*)d_in[1];
    const float* Whh0 = (const float*)d_in[2];
    const float* bih0 = (const float*)d_in[3];
    const float* bhh0 = (const float*)d_in[4];
    const float* Wih1 = (const float*)d_in[5];
    const float* Whh1 = (const float*)d_in[6];
    const float* bih1 = (const float*)d_in[7];
    const float* bhh1 = (const float*)d_in[8];
    const float* Wih2 = (const float*)d_in[9];
    const float* Whh2 = (const float*)d_in[10];
    const float* bih2 = (const float*)d_in[11];
    const float* bhh2 = (const float*)d_in[12];
    const float* Wout = (const float*)d_in[13];
    const float* bout = (const float*)d_in[14];

    const int XSMEM = (128 + 256) * LDK * (int)sizeof(__nv_bfloat16);  // 153600
    cudaFuncSetAttribute(xproj_wmma, cudaFuncAttributeMaxDynamicSharedMemorySize, XSMEM);

    dim3 rgrid(BATCH / 2), rblock(256);
    dim3 ggrid(BATCH * T_STEPS / 128), gblock(256);   // 4096 CTAs

    lstm_rec<0><<<rgrid, rblock>>>(x, Whh0, Wih0, bih0, bhh0);
    xproj_wmma<<<ggrid, gblock, XSMEM>>>(Wih1);
    lstm_rec<1><<<rgrid, rblock>>>(nullptr, Whh1, nullptr, bih1, bhh1);
    xproj_wmma<<<ggrid, gblock, XSMEM>>>(Wih2);
    lstm_rec<2><<<rgrid, rblock>>>(nullptr, Whh2, nullptr, bih2, bhh2);
    final_linear_kernel<<<(BATCH * NOUT + 255) / 256, 256>>>(Wout, bout, (float*)d_out);
}

// round 12
// speedup vs baseline: 2.0953x; 1.0301x over previous
#include <cuda_runtime.h>
#include <cuda_bf16.h>
#include <mma.h>
#include <cstdint>

using namespace nvcuda;

#define T_STEPS 2048
#define BATCH   256
#define HID     64
#define NG      256
#define NOUT    11
#define LDK     200     // A smem K-stride (elems)
#define LDB     208     // B global K-stride (elems), 416B (16B mult)
#define XK      192     // 3 * HID bf16-split K

typedef unsigned long long u64;

__device__ float g_hbuf[(size_t)BATCH * T_STEPS * HID];   // 128 MB
__device__ float g_xp[(size_t)BATCH * T_STEPS * NG];      // 512 MB
__device__ float g_hfin[BATCH * HID];
__device__ __align__(256) __nv_bfloat16 g_wsp[NG * LDB];  // split W_ih (106 KB)

// ---------------- scalar helpers (rec path, committed form) ----------------
__device__ __forceinline__ u64 pack2(float a, float b) {
    u64 r; asm("mov.b64 %0, {%1,%2};" : "=l"(r) : "f"(a), "f"(b)); return r;
}
__device__ __forceinline__ void unpack2(u64 v, float& a, float& b) {
    asm("mov.b64 {%0,%1}, %2;" : "=f"(a), "=f"(b) : "l"(v));
}
__device__ __forceinline__ void ffma2(u64& d, u64 a, u64 b) {
    asm("fma.rn.f32x2 %0, %1, %2, %0;" : "+l"(d) : "l"(a), "l"(b));
}
__device__ __forceinline__ float tanha(float x) {
    float y; asm("tanh.approx.f32 %0, %1;" : "=f"(y) : "f"(x)); return y;
}
__device__ __forceinline__ float sigt(float x) {
    return fmaf(0.5f, tanha(0.5f * x), 0.5f);
}
__device__ __forceinline__ void gbar(int id) {
    asm volatile("bar.sync %0, 128;" :: "r"(id) : "memory");
}
__device__ __forceinline__ void bsplit(float x, uint32_t& hibits, float& lo) {
    uint32_t u = __float_as_uint(x) & 0xFFFF0000u;
    hibits = u;
    lo = x - __uint_as_float(u);
}
__device__ __forceinline__ uint32_t bfpack_rn(float x0, float x1) {
    __nv_bfloat162 h = __floats2bfloat162_rn(x0, x1);
    return *(uint32_t*)&h;
}

// ---------------------------------------------------------------------------
// One-time W_ih split: row n -> [Wh | Wh | Wl] bf16, global buffer.
// ---------------------------------------------------------------------------
__global__ void wsplit(const float* __restrict__ W_ih)
{
    const int n = threadIdx.x;                 // 256 threads, 1 gate-row each
    const float4* src = (const float4*)(W_ih + n * HID);
    __nv_bfloat16* br = g_wsp + n * LDB;
#pragma unroll
    for (int i = 0; i < 8; i++) {
        float4 v = src[i * 2];
        float4 w = src[i * 2 + 1];
        uint32_t h0, h1, h2, h3, h4, h5, h6, h7;
        float l0, l1, l2, l3, l4, l5, l6, l7;
        bsplit(v.x, h0, l0); bsplit(v.y, h1, l1);
        bsplit(v.z, h2, l2); bsplit(v.w, h3, l3);
        bsplit(w.x, h4, l4); bsplit(w.y, h5, l5);
        bsplit(w.z, h6, l6); bsplit(w.w, h7, l7);
        uint32_t hp0 = (h0 >> 16) | (h1 & 0xFFFF0000u);
        uint32_t hp1 = (h2 >> 16) | (h3 & 0xFFFF0000u);
        uint32_t hp2 = (h4 >> 16) | (h5 & 0xFFFF0000u);
        uint32_t hp3 = (h6 >> 16) | (h7 & 0xFFFF0000u);
        *(uint32_t*)(br + 8 * i)           = hp0;
        *(uint32_t*)(br + 8 * i + 2)       = hp1;
        *(uint32_t*)(br + 8 * i + 4)       = hp2;
        *(uint32_t*)(br + 8 * i + 6)       = hp3;
        *(uint32_t*)(br + 64 + 8 * i)      = hp0;
        *(uint32_t*)(br + 64 + 8 * i + 2)  = hp1;
        *(uint32_t*)(br + 64 + 8 * i + 4)  = hp2;
        *(uint32_t*)(br + 64 + 8 * i + 6)  = hp3;
        *(uint32_t*)(br + 128 + 8 * i)     = bfpack_rn(l0, l1);
        *(uint32_t*)(br + 128 + 8 * i + 2) = bfpack_rn(l2, l3);
        *(uint32_t*)(br + 128 + 8 * i + 4) = bfpack_rn(l4, l5);
        *(uint32_t*)(br + 128 + 8 * i + 6) = bfpack_rn(l6, l7);
    }
}

// ---------------------------------------------------------------------------
// WMMA x-projection, v12: M=64 tile, 128 threads, 4 CTAs/SM.
// A (split h) in 25.6KB static smem; B read directly from g_wsp (L1/L2-hot).
// Warp (mw, nw): rows mw*32..+32, cols nw*128..+128.
// ---------------------------------------------------------------------------
__global__ __launch_bounds__(128, 4)
void xproj_wmma(int dummy)
{
    __shared__ __align__(16) __nv_bfloat16 As[64 * LDK];   // 25.6 KB

    const int tid = threadIdx.x;
    const int wid = tid >> 5;
    const size_t m0 = (size_t)blockIdx.x * 64;

    // ---- A fill: 2 threads per m-row, 32 floats each; [Ah | Al | Ah] ----
    {
        const int row  = tid >> 1;
        const int half = (tid & 1) * 32;
        const float4* src = (const float4*)(g_hbuf + (m0 + row) * HID + half);
        __nv_bfloat16* ar = As + row * LDK + half;
#pragma unroll
        for (int i = 0; i < 8; i++) {
            float4 v = src[i];
            uint32_t h0, h1, h2, h3; float l0, l1, l2, l3;
            bsplit(v.x, h0, l0); bsplit(v.y, h1, l1);
            bsplit(v.z, h2, l2); bsplit(v.w, h3, l3);
            uint32_t hp0 = (h0 >> 16) | (h1 & 0xFFFF0000u);
            uint32_t hp1 = (h2 >> 16) | (h3 & 0xFFFF0000u);
            *(uint32_t*)(ar + 4 * i)           = hp0;
            *(uint32_t*)(ar + 4 * i + 2)       = hp1;
            *(uint32_t*)(ar + 64 + 4 * i)      = bfpack_rn(l0, l1);
            *(uint32_t*)(ar + 64 + 4 * i + 2)  = bfpack_rn(l2, l3);
            *(uint32_t*)(ar + 128 + 4 * i)     = hp0;
            *(uint32_t*)(ar + 128 + 4 * i + 2) = hp1;
        }
    }
    __syncthreads();

    const int mw = wid & 1;
    const int nw = wid >> 1;
    const __nv_bfloat16* a0p = As + (mw * 32) * LDK;
    const __nv_bfloat16* a1p = As + (mw * 32 + 16) * LDK;

#pragma unroll
    for (int nt = 0; nt < 8; nt++) {
        const int n0 = nw * 128 + nt * 16;
        wmma::fragment<wmma::accumulator, 16, 16, 16, float> c0, c1;
        wmma::fill_fragment(c0, 0.0f);
        wmma::fill_fragment(c1, 0.0f);
#pragma unroll
        for (int k = 0; k < 12; k++) {
            wmma::fragment<wmma::matrix_a, 16, 16, 16, __nv_bfloat16, wmma::row_major> a0, a1;
            wmma::fragment<wmma::matrix_b, 16, 16, 16, __nv_bfloat16, wmma::col_major> b;
            wmma::load_matrix_sync(a0, a0p + k * 16, LDK);
            wmma::load_matrix_sync(a1, a1p + k * 16, LDK);
            wmma::load_matrix_sync(b, g_wsp + n0 * LDB + k * 16, LDB);
            wmma::mma_sync(c0, a0, b, c0);
            wmma::mma_sync(c1, a1, b, c1);
        }
        float* o = g_xp + (m0 + (size_t)(mw * 32)) * NG + n0;
        wmma::store_matrix_sync(o, c0, NG, wmma::mem_row_major);
        wmma::store_matrix_sync(o + (size_t)16 * NG, c1, NG, wmma::mem_row_major);
    }
}

// ---------------------------------------------------------------------------
// Recurrent kernel (committed R11 form, unchanged).
// ---------------------------------------------------------------------------
template<int MODE>
__global__ __launch_bounds__(256, 1)
void lstm_rec(const float* __restrict__ x_in,
              const float* __restrict__ W_hh,
              const float* __restrict__ W_ih,
              const float* __restrict__ b_ih,
              const float* __restrict__ b_hh)
{
    __shared__ __align__(16) float sh[2][2][HID];
    __shared__ float sx[2][2][2];

    const int tid  = threadIdx.x;
    const int be   = tid >> 7;
    const int r    = tid & 127;
    const int j    = r >> 1;
    const int role = r & 1;
    const int bg   = blockIdx.x * 2 + be;
    const int bid  = be + 1;

    const int rowA = role ? (64 + j) : j;         // (i|f)
    const int rowB = rowA + 128;                  // (g|o)

    u64 wA[32], wB[32];
    {
        const float4* pa = (const float4*)(W_hh + rowA * HID);
        const float4* pb = (const float4*)(W_hh + rowB * HID);
#pragma unroll
        for (int i = 0; i < 16; i++) {
            float4 va = pa[i], vb = pb[i];
            wA[2 * i] = pack2(va.x, va.y); wA[2 * i + 1] = pack2(va.z, va.w);
            wB[2 * i] = pack2(vb.x, vb.y); wB[2 * i + 1] = pack2(vb.z, vb.w);
        }
    }

    const float biasA = b_ih[rowA] + b_hh[rowA];
    const float biasB = b_ih[rowB] + b_hh[rowB];
    float wxA0 = 0.f, wxA1 = 0.f, wxB0 = 0.f, wxB1 = 0.f;
    if (MODE == 0) {
        wxA0 = W_ih[rowA * 2]; wxA1 = W_ih[rowA * 2 + 1];
        wxB0 = W_ih[rowB * 2]; wxB1 = W_ih[rowB * 2 + 1];
    }

    if (role) sh[0][be][j] = 0.f;

    float xn0 = 0.f, xn1 = 0.f;
    if (MODE == 0 && r == 0) {
        const float2* xq = (const float2*)(x_in + (size_t)bg * T_STEPS * 2);
        float2 x0 = xq[0]; sx[0][be][0] = x0.x; sx[0][be][1] = x0.y;
        float2 x1 = xq[1]; xn0 = x1.x; xn1 = x1.y;
    }

    const float* xpb = g_xp + (size_t)bg * T_STEPS * NG;
    float xpA0 = 0.f, xpB0 = 0.f, xpA1 = 0.f, xpB1 = 0.f;
    if (MODE >= 1) {
        xpA0 = xpb[rowA];      xpB0 = xpb[rowB];
        xpA1 = xpb[NG + rowA]; xpB1 = xpb[NG + rowB];
    }

    float c = 0.f;
    float* hb = g_hbuf + (size_t)bg * T_STEPS * HID + j;
    __syncthreads();

    for (int t = 0; t < T_STEPS; t++) {
        const int p = t & 1;
        const ulonglong2* hr = (const ulonglong2*)sh[p][be];
        u64 aA0 = 0, aA1 = 0, aB0 = 0, aB1 = 0;
#pragma unroll
        for (int k = 0; k < 16; k++) {
            ulonglong2 pv = hr[k];                 // broadcast LDS.128
            ffma2(aA0, pv.x, wA[2 * k]); ffma2(aA1, pv.y, wA[2 * k + 1]);
            ffma2(aB0, pv.x, wB[2 * k]); ffma2(aB1, pv.y, wB[2 * k + 1]);
        }
        float zA, zB;
        {
            float u0, u1, u2, u3;
            unpack2(aA0, u0, u1); unpack2(aA1, u2, u3); zA = (u0 + u1) + (u2 + u3);
            unpack2(aB0, u0, u1); unpack2(aB1, u2, u3); zB = (u0 + u1) + (u2 + u3);
        }
        if (MODE == 0) {
            float xv0 = sx[p][be][0], xv1 = sx[p][be][1];
            zA += biasA + wxA0 * xv0 + wxA1 * xv1;
            zB += biasB + wxB0 * xv0 + wxB1 * xv1;
        } else {
            zA += xpA0 + biasA; zB += xpB0 + biasB;
        }

        if (MODE >= 1) {
            xpA0 = xpA1; xpB0 = xpB1;
            int tn = (t + 2 < T_STEPS) ? (t + 2) : (T_STEPS - 1);
            xpA1 = xpb[(size_t)tn * NG + rowA];
            xpB1 = xpb[(size_t)tn * NG + rowB];
        }

        float sA    = sigt(zA);                        // sig(i) | sig(f)
        float other = role ? sigt(zB) : tanha(zB);     // sig(o) | tanh(g)
        float send  = sA * other;                      // i*tanh(g) | --
        float ar    = __shfl_xor_sync(0xffffffffu, send, 1);
        if (role) {
            c = sA * c + ar;
            float h = other * tanha(c);
            sh[p ^ 1][be][j] = h;
            if (MODE <= 1) hb[(size_t)t * HID] = h;
            if (MODE == 2 && t == T_STEPS - 1) g_hfin[bg * HID + j] = h;
        }
        if (MODE == 0 && r == 0) {
            sx[p ^ 1][be][0] = xn0; sx[p ^ 1][be][1] = xn1;
            int tn = (t + 2 < T_STEPS) ? (t + 2) : (T_STEPS - 1);
            const float2* xq = (const float2*)(x_in + (size_t)bg * T_STEPS * 2);
            float2 xv = xq[tn]; xn0 = xv.x; xn1 = xv.y;
        }
        gbar(bid);
    }
}

__global__ void final_linear_kernel(const float* __restrict__ W_out,
                                    const float* __restrict__ b_out,
                                    float* __restrict__ out)
{
    int idx = blockIdx.x * blockDim.x + threadIdx.x;
    if (idx >= BATCH * NOUT) return;
    int b = idx / NOUT, o = idx - b * NOUT;
    float s = b_out[o];
    const float* h  = &g_hfin[b * HID];
    const float* wr = &W_out[o * HID];
#pragma unroll 16
    for (int k = 0; k < HID; k++) s += h[k] * wr[k];
    out[idx] = s;
}

extern "C" void kernel_launch(void* const* d_in, const int* in_sizes, int n_in,
                              void* d_out, int out_size)
{
    const float* x    = (const float*)d_in[0];
    const float* Wih0 = (const float*)d_in[1];
    const float* Whh0 = (const float*)d_in[2];
    const float* bih0 = (const float*)d_in[3];
    const float* bhh0 = (const float*)d_in[4];
    const float* Wih1 = (const float*)d_in[5];
    const float* Whh1 = (const float*)d_in[6];
    const float* bih1 = (const float*)d_in[7];
    const float* bhh1 = (const float*)d_in[8];
    const float* Wih2 = (const float*)d_in[9];
    const float* Whh2 = (const float*)d_in[10];
    const float* bih2 = (const float*)d_in[11];
    const float* bhh2 = (const float*)d_in[12];
    const float* Wout = (const float*)d_in[13];
    const float* bout = (const float*)d_in[14];

    dim3 rgrid(BATCH / 2), rblock(256);
    dim3 ggrid(BATCH * T_STEPS / 64), gblock(128);    // 8192 CTAs, 4/SM

    lstm_rec<0><<<rgrid, rblock>>>(x, Whh0, Wih0, bih0, bhh0);
    wsplit<<<1, 256>>>(Wih1);
    xproj_wmma<<<ggrid, gblock>>>(0);
    lstm_rec<1><<<rgrid, rblock>>>(nullptr, Whh1, nullptr, bih1, bhh1);
    wsplit<<<1, 256>>>(Wih2);
    xproj_wmma<<<ggrid, gblock>>>(0);
    lstm_rec<2><<<rgrid, rblock>>>(nullptr, Whh2, nullptr, bih2, bhh2);
    final_linear_kernel<<<(BATCH * NOUT + 255) / 256, 256>>>(Wout, bout, (float*)d_out);
}